// round 3
// baseline (speedup 1.0000x reference)
#include <cuda_runtime.h>
#include <cstdint>

// Problem constants (fixed by the reference)
#define NUM_USERS 100000
#define NUM_ITEMS 50000
#define N_NODES   150000   // NUM_USERS + NUM_ITEMS
#define DIM       128      // LATENT_DIM * K
#define BATCHSZ   4096

// Scratch: 3 layer buffers (76.8 MB each) + dst-needed flags.
// __device__ globals per harness allocation rules.
__device__ float g_x1[(size_t)N_NODES * DIM];
__device__ float g_x2[(size_t)N_NODES * DIM];
__device__ float g_x3[(size_t)N_NODES * DIM];
__device__ unsigned char g_flag[N_NODES];

// ---------------------------------------------------------------------------
// Zero x1, x2 (full) and flags. x3 is zeroed only at flagged rows (flag kernel).
// ---------------------------------------------------------------------------
__global__ void zero_kernel() {
    const size_t stride = (size_t)gridDim.x * blockDim.x;
    size_t tid = (size_t)blockIdx.x * blockDim.x + threadIdx.x;
    const size_t total4 = (size_t)N_NODES * DIM / 4;
    float4 z = make_float4(0.f, 0.f, 0.f, 0.f);
    float4* p1 = reinterpret_cast<float4*>(g_x1);
    float4* p2 = reinterpret_cast<float4*>(g_x2);
    for (size_t i = tid; i < total4; i += stride) {
        p1[i] = z;
        p2[i] = z;
    }
    for (size_t i = tid; i < N_NODES; i += stride) g_flag[i] = 0;
}

// ---------------------------------------------------------------------------
// Mark batch rows as needed for layer 3, and zero their x3 rows.
// One warp per batch element (2*BATCH warps). Duplicate rows race on
// identical writes (flag=1, row=0) — benign.
// ---------------------------------------------------------------------------
__global__ void flag_kernel(const int* __restrict__ users,
                            const int* __restrict__ items, int batch) {
    int w    = (blockIdx.x * blockDim.x + threadIdx.x) >> 5;
    int lane = threadIdx.x & 31;
    if (w >= 2 * batch) return;
    int row = (w < batch) ? users[w] : (NUM_USERS + items[w - batch]);
    if (lane == 0) g_flag[row] = 1;
    // 32 lanes x float4 = 128 floats = one row
    reinterpret_cast<float4*>(g_x3 + (size_t)row * DIM)[lane] =
        make_float4(0.f, 0.f, 0.f, 0.f);
}

// ---------------------------------------------------------------------------
// SpMM: xout[dst] += val * xin[src], one warp handles 32 edges.
// LAYER=1 reads the input embeddings (virtual concat), writes g_x1.
// LAYER=2 reads g_x1, writes g_x2.
// LAYER=3 reads g_x2, writes g_x3, gated on g_flag[dst] (only ~5.5% of
//         edges touch a needed output row).
// ---------------------------------------------------------------------------
template <int LAYER>
__global__ void spmm_kernel(const float* __restrict__ user_emb,
                            const float* __restrict__ item_emb,
                            const int*   __restrict__ src,
                            const int*   __restrict__ dst,
                            const float* __restrict__ val,
                            int n_edges) {
    const int warp = (blockIdx.x * blockDim.x + threadIdx.x) >> 5;
    const int lane = threadIdx.x & 31;
    const int base = warp * 32;
    if (base >= n_edges) return;

    // Coalesced edge-metadata loads: one edge per lane.
    int   s = 0, d = 0;
    float v = 0.f;
    int   f = 0;
    const int e = base + lane;
    if (e < n_edges) {
        s = src[e];
        d = dst[e];
        v = val[e];
        f = (LAYER == 3) ? (int)g_flag[d] : 1;
    }

    const int cnt = min(32, n_edges - base);
    for (int j = 0; j < cnt; j++) {
        if (LAYER == 3) {
            // warp-uniform gate: skip edges whose dst row is never consumed
            if (__shfl_sync(0xffffffffu, f, j) == 0) continue;
        }
        const int   ss = __shfl_sync(0xffffffffu, s, j);
        const int   dd = __shfl_sync(0xffffffffu, d, j);
        const float vv = __shfl_sync(0xffffffffu, v, j);

        const float4* srow;
        if (LAYER == 1) {
            srow = (ss < NUM_USERS)
                 ? reinterpret_cast<const float4*>(user_emb + (size_t)ss * DIM)
                 : reinterpret_cast<const float4*>(item_emb + (size_t)(ss - NUM_USERS) * DIM);
        } else if (LAYER == 2) {
            srow = reinterpret_cast<const float4*>(g_x1 + (size_t)ss * DIM);
        } else {
            srow = reinterpret_cast<const float4*>(g_x2 + (size_t)ss * DIM);
        }
        float4 m = srow[lane];

        float* drow;
        if (LAYER == 1)      drow = g_x1 + (size_t)dd * DIM;
        else if (LAYER == 2) drow = g_x2 + (size_t)dd * DIM;
        else                 drow = g_x3 + (size_t)dd * DIM;

        // vector reduction: 4x fewer atomic ops than scalar atomicAdd
        asm volatile("red.global.add.v4.f32 [%0], {%1, %2, %3, %4};"
                     :: "l"(drow + 4 * lane),
                        "f"(m.x * vv), "f"(m.y * vv), "f"(m.z * vv), "f"(m.w * vv)
                     : "memory");
    }
}

// ---------------------------------------------------------------------------
// Final: out[b] = dot( mean(x0..x3)[user_b], mean(x0..x3)[item_b] )
//       = dot( sum_u, sum_i ) / 16.  One warp per batch element.
// ---------------------------------------------------------------------------
__global__ void dot_kernel(const float* __restrict__ user_emb,
                           const float* __restrict__ item_emb,
                           const int*   __restrict__ users,
                           const int*   __restrict__ items,
                           float* __restrict__ out, int batch) {
    int w    = (blockIdx.x * blockDim.x + threadIdx.x) >> 5;
    int lane = threadIdx.x & 31;
    if (w >= batch) return;

    const int u  = users[w];
    const int it = items[w];
    const size_t ru = (size_t)u * DIM;
    const size_t ri = (size_t)(NUM_USERS + it) * DIM;

    float4 a0 = reinterpret_cast<const float4*>(user_emb + ru)[lane];
    float4 a1 = reinterpret_cast<const float4*>(g_x1 + ru)[lane];
    float4 a2 = reinterpret_cast<const float4*>(g_x2 + ru)[lane];
    float4 a3 = reinterpret_cast<const float4*>(g_x3 + ru)[lane];

    float4 b0 = reinterpret_cast<const float4*>(item_emb + (size_t)it * DIM)[lane];
    float4 b1 = reinterpret_cast<const float4*>(g_x1 + ri)[lane];
    float4 b2 = reinterpret_cast<const float4*>(g_x2 + ri)[lane];
    float4 b3 = reinterpret_cast<const float4*>(g_x3 + ri)[lane];

    float sux = a0.x + a1.x + a2.x + a3.x;
    float suy = a0.y + a1.y + a2.y + a3.y;
    float suz = a0.z + a1.z + a2.z + a3.z;
    float suw = a0.w + a1.w + a2.w + a3.w;

    float six = b0.x + b1.x + b2.x + b3.x;
    float siy = b0.y + b1.y + b2.y + b3.y;
    float siz = b0.z + b1.z + b2.z + b3.z;
    float siw = b0.w + b1.w + b2.w + b3.w;

    float p = sux * six + suy * siy + suz * siz + suw * siw;

    #pragma unroll
    for (int off = 16; off > 0; off >>= 1)
        p += __shfl_xor_sync(0xffffffffu, p, off);

    if (lane == 0) out[w] = p * 0.0625f;  // mean /4 on each side -> /16
}

// ---------------------------------------------------------------------------
extern "C" void kernel_launch(void* const* d_in, const int* in_sizes, int n_in,
                              void* d_out, int out_size) {
    const float* user_emb = (const float*)d_in[0];
    const float* item_emb = (const float*)d_in[1];
    const int*   src      = (const int*)  d_in[2];
    const int*   dst      = (const int*)  d_in[3];
    const float* val      = (const float*)d_in[4];
    const int*   users    = (const int*)  d_in[5];
    const int*   items    = (const int*)  d_in[6];
    float*       out      = (float*)d_out;

    const int n_edges = in_sizes[2];
    const int batch   = in_sizes[5];

    // 1. zero x1/x2 + flags
    zero_kernel<<<2048, 256>>>();

    // 2. set flags + zero the (few) x3 rows that will be written
    {
        int threads = 2 * batch * 32;
        flag_kernel<<<(threads + 255) / 256, 256>>>(users, items, batch);
    }

    // 3. three SpMM layers (layer 3 gated on needed dst rows)
    const int warps  = (n_edges + 31) / 32;
    const int blocks = (warps + 7) / 8;   // 256 threads = 8 warps per block
    spmm_kernel<1><<<blocks, 256>>>(user_emb, item_emb, src, dst, val, n_edges);
    spmm_kernel<2><<<blocks, 256>>>(user_emb, item_emb, src, dst, val, n_edges);
    spmm_kernel<3><<<blocks, 256>>>(user_emb, item_emb, src, dst, val, n_edges);

    // 4. batched mean+dot
    {
        int threads = batch * 32;
        dot_kernel<<<(threads + 255) / 256, 256>>>(user_emb, item_emb,
                                                   users, items, out, batch);
    }
}